// round 5
// baseline (speedup 1.0000x reference)
#include <cuda_runtime.h>
#include <cuda_bf16.h>

#define IMG_H 384
#define IMG_W 640
#define N_PLANES 96            // 32 * 3
#define WIN 11
#define HALO 5
#define OUT_W_TILE 246
#define NX 3                   // 246 + 246 + 148 = 640
#define NY 2
#define ROWS_PER_BLK (IMG_H / NY)     // 192
#define CHUNK 16
#define NCHUNKS (ROWS_PER_BLK / CHUNK)  // 12
#define NTHREADS 256
#define VSTRIDE 257            // 257 % 32 == 1 -> conflict-free both phases
#define SMEM_FLOATS (5 * CHUNK * VSTRIDE)
#define SMEM_BYTES (SMEM_FLOATS * 4)
#define SSIM_C1 1e-4f
#define SSIM_C2 9e-4f
#define N_BLOCKS (NX * NY * N_PLANES)  // 576

__device__ float g_partials[N_BLOCKS];

__global__ __launch_bounds__(NTHREADS, 2)
void ssim_main(const float* __restrict__ pred, const float* __restrict__ targ) {
    extern __shared__ float smem[];
    // vbuf layout: smem[(q*CHUNK + row)*VSTRIDE + col], q in [0,5)

    const int b = blockIdx.x;
    const int xt = b % NX;
    const int yt = (b / NX) % NY;
    const int plane = b / (NX * NY);

    const int x0 = xt * OUT_W_TILE;
    const int outw = min(OUT_W_TILE, IMG_W - x0);   // 246 or 148
    const int inw = outw + 2 * HALO;
    const int r0 = yt * ROWS_PER_BLK;

    const size_t poff = (size_t)plane * (IMG_H * IMG_W);
    const float* __restrict__ P = pred + poff;
    const float* __restrict__ T = targ + poff;

    // ---------- vertical-pass identity ----------
    const int c = threadIdx.x;               // buffer column
    const int gx = x0 - HALO + c;            // global column
    const bool cvalid = (c < inw);
    const bool colin = cvalid && (gx >= 0) && (gx < IMG_W);

    // running vertical sums over input rows [r-5, r+5]
    float vs0 = 0.f, vs1 = 0.f, vs2 = 0.f, vs3 = 0.f, vs4 = 0.f;

    // warmup: rows r0-5 .. r0+4
    #pragma unroll
    for (int k = -HALO; k < HALO; ++k) {
        const int rr = r0 + k;
        float p = 0.f, t = 0.f;
        if (colin && rr >= 0 && rr < IMG_H) {
            p = P[(size_t)rr * IMG_W + gx];
            t = T[(size_t)rr * IMG_W + gx];
        }
        vs0 += p; vs1 += t;
        vs2 = fmaf(p, p, vs2); vs3 = fmaf(t, t, vs3); vs4 = fmaf(p, t, vs4);
    }

    // ---------- horizontal-pass identity ----------
    const int hrow = threadIdx.x & (CHUNK - 1);   // 0..15
    const int hseg = threadIdx.x >> 4;            // 0..15
    const int xs = hseg * 16;

    float acc = 0.f;
    const float inv = 1.0f / 121.0f;

    for (int ch = 0; ch < NCHUNKS; ++ch) {
        const int rbase = r0 + ch * CHUNK;

        // ===== vertical pass: produce CHUNK rows of 5 box-column sums =====
        #pragma unroll
        for (int i = 0; i < CHUNK; ++i) {
            const int r = rbase + i;
            {   // incoming row r+5
                const int rr = r + HALO;
                float p = 0.f, t = 0.f;
                if (colin && rr < IMG_H) {
                    p = P[(size_t)rr * IMG_W + gx];
                    t = T[(size_t)rr * IMG_W + gx];
                }
                vs0 += p; vs1 += t;
                vs2 = fmaf(p, p, vs2); vs3 = fmaf(t, t, vs3); vs4 = fmaf(p, t, vs4);
            }
            if (cvalid) {
                smem[(0 * CHUNK + i) * VSTRIDE + c] = vs0;
                smem[(1 * CHUNK + i) * VSTRIDE + c] = vs1;
                smem[(2 * CHUNK + i) * VSTRIDE + c] = vs2;
                smem[(3 * CHUNK + i) * VSTRIDE + c] = vs3;
                smem[(4 * CHUNK + i) * VSTRIDE + c] = vs4;
            }
            {   // outgoing row r-5 (L1-resident reload)
                const int ro = r - HALO;
                float p = 0.f, t = 0.f;
                if (colin && ro >= 0) {
                    p = P[(size_t)ro * IMG_W + gx];
                    t = T[(size_t)ro * IMG_W + gx];
                }
                vs0 -= p; vs1 -= t;
                vs2 = fmaf(-p, p, vs2); vs3 = fmaf(-t, t, vs3); vs4 = fmaf(-p, t, vs4);
            }
        }
        __syncthreads();

        // ===== horizontal pass: slide an 11-wide window along this segment =====
        if (xs < outw) {
            const float* __restrict__ row0 = smem + (0 * CHUNK + hrow) * VSTRIDE;
            const float* __restrict__ row1 = smem + (1 * CHUNK + hrow) * VSTRIDE;
            const float* __restrict__ row2 = smem + (2 * CHUNK + hrow) * VSTRIDE;
            const float* __restrict__ row3 = smem + (3 * CHUNK + hrow) * VSTRIDE;
            const float* __restrict__ row4 = smem + (4 * CHUNK + hrow) * VSTRIDE;

            float s0 = 0.f, s1 = 0.f, s2 = 0.f, s3 = 0.f, s4 = 0.f;
            #pragma unroll
            for (int j = 0; j < WIN; ++j) {
                s0 += row0[xs + j];
                s1 += row1[xs + j];
                s2 += row2[xs + j];
                s3 += row3[xs + j];
                s4 += row4[xs + j];
            }

            const int xe = min(xs + 16, outw);
            #pragma unroll
            for (int j = 0; j < 16; ++j) {
                const int x = xs + j;
                if (x >= xe) break;

                const float mp  = s0 * inv;
                const float mt  = s1 * inv;
                const float epp = s2 * inv;
                const float ett = s3 * inv;
                const float ept = s4 * inv;
                const float sp  = epp - mp * mp;
                const float st  = ett - mt * mt;
                const float spt = ept - mp * mt;
                const float num = (2.f * mp * mt + SSIM_C1) * (2.f * spt + SSIM_C2);
                const float den = (mp * mp + mt * mt + SSIM_C1) * (sp + st + SSIM_C2);
                acc += __fdividef(num, den);

                if (x + 1 < xe) {   // slide window: +col(x+11), -col(x)
                    s0 += row0[x + WIN] - row0[x];
                    s1 += row1[x + WIN] - row1[x];
                    s2 += row2[x + WIN] - row2[x];
                    s3 += row3[x + WIN] - row3[x];
                    s4 += row4[x + WIN] - row4[x];
                }
            }
        }
        __syncthreads();
    }

    // ---------- deterministic block reduction ----------
    smem[threadIdx.x] = acc;
    __syncthreads();
    #pragma unroll
    for (int off = NTHREADS / 2; off > 0; off >>= 1) {
        if (threadIdx.x < off) smem[threadIdx.x] += smem[threadIdx.x + off];
        __syncthreads();
    }
    if (threadIdx.x == 0) g_partials[b] = smem[0];
}

__global__ void ssim_finalize(float* __restrict__ out) {
    __shared__ double sd[256];
    double s = 0.0;
    for (int i = threadIdx.x; i < N_BLOCKS; i += 256) {
        s += (double)g_partials[i];
    }
    sd[threadIdx.x] = s;
    __syncthreads();
    #pragma unroll
    for (int off = 128; off > 0; off >>= 1) {
        if (threadIdx.x < off) sd[threadIdx.x] += sd[threadIdx.x + off];
        __syncthreads();
    }
    if (threadIdx.x == 0) {
        const double n = (double)N_PLANES * IMG_H * IMG_W;   // 23,592,960
        out[0] = (float)(1.0 - sd[0] / n);
    }
}

extern "C" void kernel_launch(void* const* d_in, const int* in_sizes, int n_in,
                              void* d_out, int out_size) {
    const float* pred = (const float*)d_in[0];
    const float* targ = (const float*)d_in[1];
    float* out = (float*)d_out;

    // 82,240 B dynamic SMEM > 48 KB default -> opt in (idempotent, capture-safe)
    cudaFuncSetAttribute(ssim_main, cudaFuncAttributeMaxDynamicSharedMemorySize,
                         SMEM_BYTES);

    ssim_main<<<N_BLOCKS, NTHREADS, SMEM_BYTES>>>(pred, targ);
    ssim_finalize<<<1, 256>>>(out);
}

// round 6
// speedup vs baseline: 1.3972x; 1.3972x over previous
#include <cuda_runtime.h>
#include <cuda_bf16.h>

#define IMG_H 384
#define IMG_W 640
#define N_PLANES 96            // 32 * 3
#define WIN 11
#define HALO 5
#define OUT_W_TILE 246
#define NX 3                   // 246 + 246 + 148 = 640
#define NY 2
#define ROWS_PER_BLK (IMG_H / NY)       // 192
#define CHUNK 16
#define NCHUNKS (ROWS_PER_BLK / CHUNK)  // 12
#define NTHREADS 256

// SMEM layout (float units):
//   A01: CHUNK rows of VS2 float2 pairs (Sp, St)    -- packed
//   A23: CHUNK rows of VS1 floats      (Spp + Stt)
//   A4 : CHUNK rows of VS1 floats      (Spt)
// VS2=258: 2*VS2 = 516 == 4 (mod 32)  -> conflict-free 8-lane LDS.128 phases
// VS1=260: VS1 == 4 (mod 32)          -> conflict-free 8-lane LDS.128 phases
#define VS2 258
#define VS1 260
#define A01_OFF 0
#define A23_OFF (CHUNK * VS2 * 2)            // 8256
#define A4_OFF  (A23_OFF + CHUNK * VS1)      // 12416
#define SMEM_FLOATS (A4_OFF + CHUNK * VS1 + 64)  // 16640 (incl. overread pad)
#define SMEM_BYTES (SMEM_FLOATS * 4)             // 66560 B

#define C1F 1e-4f
#define C2F 9e-4f
#define N_BLOCKS (NX * NY * N_PLANES)  // 576

__device__ float g_partials[N_BLOCKS];
__device__ unsigned int g_count = 0;

// ---- packed f32x2 helpers (Blackwell FFMA2 path) ----
__device__ __forceinline__ unsigned long long pk2(float lo, float hi) {
    unsigned long long r;
    asm("mov.b64 %0, {%1, %2};" : "=l"(r) : "f"(lo), "f"(hi));
    return r;
}
__device__ __forceinline__ void upk2(unsigned long long v, float& lo, float& hi) {
    asm("mov.b64 {%0, %1}, %2;" : "=f"(lo), "=f"(hi) : "l"(v));
}
__device__ __forceinline__ unsigned long long add2(unsigned long long a, unsigned long long b) {
    unsigned long long r;
    asm("add.rn.f32x2 %0, %1, %2;" : "=l"(r) : "l"(a), "l"(b));
    return r;
}
__device__ __forceinline__ unsigned long long fma2(unsigned long long a, unsigned long long b,
                                                   unsigned long long c) {
    unsigned long long r;
    asm("fma.rn.f32x2 %0, %1, %2, %3;" : "=l"(r) : "l"(a), "l"(b), "l"(c));
    return r;
}
#define NEG1_X2 0xBF800000BF800000ULL   // packed (-1.0f, -1.0f)

__global__ __launch_bounds__(NTHREADS, 2)
void ssim_main(const float* __restrict__ pred, const float* __restrict__ targ,
               float* __restrict__ out) {
    extern __shared__ float smem[];

    const int b = blockIdx.x;
    const int xt = b % NX;
    const int yt = (b / NX) % NY;
    const int plane = b / (NX * NY);

    const int x0 = xt * OUT_W_TILE;
    const int outw = min(OUT_W_TILE, IMG_W - x0);   // 246 or 148
    const int inw = outw + 2 * HALO;
    const int r0 = yt * ROWS_PER_BLK;

    const size_t poff = (size_t)plane * (IMG_H * IMG_W);
    const float* __restrict__ P = pred + poff;
    const float* __restrict__ T = targ + poff;

    // ---------- vertical-pass identity ----------
    const int c = threadIdx.x;               // buffer column
    const int gx = x0 - HALO + c;            // global column
    const bool cvalid = (c < inw);
    const bool colin = cvalid && (gx >= 0) && (gx < IMG_W);

    unsigned long long vs01 = 0ULL;          // packed (sum p, sum t)
    float vs23 = 0.f;                        // sum (p*p + t*t)
    float vs4 = 0.f;                         // sum (p*t)

    #pragma unroll
    for (int k = -HALO; k < HALO; ++k) {
        const int rr = r0 + k;
        float p = 0.f, t = 0.f;
        if (colin && rr >= 0 && rr < IMG_H) {
            p = P[rr * IMG_W + gx];
            t = T[rr * IMG_W + gx];
        }
        vs01 = add2(vs01, pk2(p, t));
        vs23 = fmaf(p, p, fmaf(t, t, vs23));
        vs4  = fmaf(p, t, vs4);
    }

    // ---------- horizontal-pass identity ----------
    const int hrow = threadIdx.x & (CHUNK - 1);   // 0..15
    const int hseg = threadIdx.x >> 4;            // 0..15
    const int xs = hseg * 16;
    const bool segvalid = (xs < outw);
    const int nvalid = segvalid ? min(16, outw - xs) : 0;

    float acc = 0.f;
    const float KK  = 1.0f / 121.0f;
    const float K2C = KK * KK;
    const float TK2 = 2.0f * K2C;
    const float C12 = C1F + C2F;

    for (int ch = 0; ch < NCHUNKS; ++ch) {
        const int rbase = r0 + ch * CHUNK;

        // ===== vertical pass: produce CHUNK rows of 4 box-column quantities =====
        #pragma unroll
        for (int i = 0; i < CHUNK; ++i) {
            const int r = rbase + i;
            {   // incoming row r+5
                const int rr = r + HALO;
                float p = 0.f, t = 0.f;
                if (colin && rr < IMG_H) {
                    p = P[rr * IMG_W + gx];
                    t = T[rr * IMG_W + gx];
                }
                vs01 = add2(vs01, pk2(p, t));
                vs23 = fmaf(p, p, fmaf(t, t, vs23));
                vs4  = fmaf(p, t, vs4);
            }
            if (cvalid) {
                *reinterpret_cast<unsigned long long*>(
                    &smem[A01_OFF + (i * VS2 + c) * 2]) = vs01;     // STS.64
                smem[A23_OFF + i * VS1 + c] = vs23;
                smem[A4_OFF  + i * VS1 + c] = vs4;
            }
            {   // outgoing row r-5 (L1-resident reload)
                const int ro = r - HALO;
                float p = 0.f, t = 0.f;
                if (colin && ro >= 0) {
                    p = P[ro * IMG_W + gx];
                    t = T[ro * IMG_W + gx];
                }
                vs01 = fma2(pk2(p, t), NEG1_X2, vs01);
                vs23 = fmaf(-p, p, fmaf(-t, t, vs23));
                vs4  = fmaf(-p, t, vs4);
            }
        }
        __syncthreads();

        // ===== horizontal pass: vectorized register-window sliding sums =====
        if (segvalid) {
            float numA[16], denF[16];

            // Pass A: packed (Sp, St) -> numA = 2k^2*ab + C1, denA = k^2*(a^2+b^2) + C1
            {
                const ulonglong2* b01 =
                    reinterpret_cast<const ulonglong2*>(smem) + ((hrow * VS2 + xs) >> 1);
                unsigned long long v[28];
                #pragma unroll
                for (int k = 0; k < 14; ++k) {
                    ulonglong2 u = b01[k];          // LDS.128, conflict-free
                    v[2 * k] = u.x; v[2 * k + 1] = u.y;
                }
                unsigned long long S = v[0];
                #pragma unroll
                for (int k = 1; k < WIN; ++k) S = add2(S, v[k]);
                #pragma unroll
                for (int j = 0; j < 16; ++j) {
                    float a, bb; upk2(S, a, bb);
                    float ab = a * bb;
                    float V  = fmaf(a, a, bb * bb);
                    numA[j] = fmaf(TK2, ab, C1F);
                    denF[j] = fmaf(K2C, V, C1F);    // den1 (for now)
                    if (j < 15) {
                        S = add2(S, v[j + WIN]);
                        S = fma2(v[j], NEG1_X2, S);
                    }
                }
            }
            // Pass B: S = box sum of (pp+tt); den2 = k*S - den1 + (C1+C2); denF = den1*den2
            {
                const float4* b23 =
                    reinterpret_cast<const float4*>(&smem[A23_OFF + hrow * VS1 + xs]);
                float w[28];
                #pragma unroll
                for (int k = 0; k < 7; ++k) {
                    float4 u = b23[k];
                    w[4*k] = u.x; w[4*k+1] = u.y; w[4*k+2] = u.z; w[4*k+3] = u.w;
                }
                float S = w[0];
                #pragma unroll
                for (int k = 1; k < WIN; ++k) S += w[k];
                #pragma unroll
                for (int j = 0; j < 16; ++j) {
                    float den1 = denF[j];
                    float den2 = fmaf(KK, S, C12 - den1);
                    denF[j] = den1 * den2;
                    if (j < 15) S += w[j + WIN] - w[j];
                }
            }
            // Pass C: S = box sum of pt; num2 = 2k*S - num1 + (C1+C2); acc += num/den
            {
                const float4* b4 =
                    reinterpret_cast<const float4*>(&smem[A4_OFF + hrow * VS1 + xs]);
                float w[28];
                #pragma unroll
                for (int k = 0; k < 7; ++k) {
                    float4 u = b4[k];
                    w[4*k] = u.x; w[4*k+1] = u.y; w[4*k+2] = u.z; w[4*k+3] = u.w;
                }
                float S = w[0];
                #pragma unroll
                for (int k = 1; k < WIN; ++k) S += w[k];
                #pragma unroll
                for (int j = 0; j < 16; ++j) {
                    float n1 = numA[j];
                    float n2 = fmaf(2.0f * KK, S, C12 - n1);
                    float r = __fdividef(n1 * n2, denF[j]);
                    if (j < nvalid) acc += r;
                    if (j < 15) S += w[j + WIN] - w[j];
                }
            }
        }
        __syncthreads();
    }

    // ---------- deterministic block reduction ----------
    smem[threadIdx.x] = acc;
    __syncthreads();
    #pragma unroll
    for (int off = NTHREADS / 2; off > 0; off >>= 1) {
        if (threadIdx.x < off) smem[threadIdx.x] += smem[threadIdx.x + off];
        __syncthreads();
    }

    // ---------- fused finalize: last block reduces all partials ----------
    __shared__ bool s_last;
    if (threadIdx.x == 0) {
        g_partials[b] = smem[0];
        __threadfence();
        unsigned int n = atomicAdd(&g_count, 1u);
        s_last = (n == (unsigned int)(N_BLOCKS - 1));
    }
    __syncthreads();
    if (s_last) {
        double* sd = reinterpret_cast<double*>(smem);
        if (threadIdx.x < 64) {
            double s = 0.0;
            #pragma unroll
            for (int q = 0; q < 9; ++q)          // 64 * 9 = 576, fixed order
                s += (double)g_partials[threadIdx.x * 9 + q];
            sd[threadIdx.x] = s;
        }
        __syncthreads();
        #pragma unroll
        for (int off = 32; off > 0; off >>= 1) {
            if (threadIdx.x < off) sd[threadIdx.x] += sd[threadIdx.x + off];
            __syncthreads();
        }
        if (threadIdx.x == 0) {
            const double n = (double)N_PLANES * IMG_H * IMG_W;   // 23,592,960
            out[0] = (float)(1.0 - sd[0] / n);
            g_count = 0u;                         // reset for next graph replay
        }
    }
}

extern "C" void kernel_launch(void* const* d_in, const int* in_sizes, int n_in,
                              void* d_out, int out_size) {
    const float* pred = (const float*)d_in[0];
    const float* targ = (const float*)d_in[1];
    float* out = (float*)d_out;

    cudaFuncSetAttribute(ssim_main, cudaFuncAttributeMaxDynamicSharedMemorySize,
                         SMEM_BYTES);
    ssim_main<<<N_BLOCKS, NTHREADS, SMEM_BYTES>>>(pred, targ, out);
}